// round 10
// baseline (speedup 1.0000x reference)
#include <cuda_runtime.h>
#include <cstdint>
#include <cstddef>

#define NB 64
#define NC 512
#define ND 1024
#define NG 8

// ---------------- scratch (device globals: no allocation allowed) ----------------
__device__ float g_u[(size_t)NB * NC * ND];     // 128 MB: u = Wzt @ v
__device__ float g_s[(size_t)NB * NC * NC];     // 64 MB: S_b = Q_b K_b^T
__device__ float g_m[(size_t)NG * NC * NC];     // 8 MB:  M_g = Wp_g^T Wg_g
__device__ float g_wzt[NC * NC];                // blockdiag(Wz) @ Wt
__device__ float g_att[NB * NG];
__device__ float g_sums[NB * NG];
__device__ float g_sumsq[NB * NG];
__device__ float g_cA[NB * NC];
__device__ float g_cB[NB * NC];

// ---------------- helpers ----------------
__device__ __forceinline__ uint32_t smem_u32(const void* p) {
    return (uint32_t)__cvta_generic_to_shared(p);
}
#define CP_ASYNC16(dst, src) \
    asm volatile("cp.async.ca.shared.global [%0], [%1], 16;" :: "r"(dst), "l"(src) : "memory")
#define CP_COMMIT() asm volatile("cp.async.commit_group;" ::: "memory")
#define CP_WAIT(n)  asm volatile("cp.async.wait_group %0;" :: "n"(n) : "memory")

__device__ __forceinline__ void mma_tf32(float c[4], const uint32_t a[4], const uint32_t b[2]) {
    asm volatile(
        "mma.sync.aligned.m16n8k8.row.col.f32.tf32.tf32.f32 "
        "{%0,%1,%2,%3}, {%4,%5,%6,%7}, {%8,%9}, {%0,%1,%2,%3};"
        : "+f"(c[0]), "+f"(c[1]), "+f"(c[2]), "+f"(c[3])
        : "r"(a[0]), "r"(a[1]), "r"(a[2]), "r"(a[3]), "r"(b[0]), "r"(b[1]));
}

// tf32 "big" part == exactly what the tensor core keeps (truncate 13 mantissa bits)
__device__ __forceinline__ uint32_t tf32_big(float x) {
    return __float_as_uint(x) & 0xFFFFE000u;
}
__device__ __forceinline__ uint32_t tf32_small(float x, uint32_t big) {
    return __float_as_uint(x - __uint_as_float(big));
}

// ---------------- tiny kernels ----------------
__global__ void zero_kernel() {
    int i = threadIdx.x;  // 512 = NB*NG
    g_att[i] = 0.f; g_sums[i] = 0.f; g_sumsq[i] = 0.f;
}

// Wzt[o, c] = sum_cl Wz[g, o%64, cl] * Wt[g*64 + cl, c],  g = o/64
__global__ void wzt_kernel(const float* __restrict__ Wt, const float* __restrict__ Wz) {
    __shared__ float wz[64];
    int o = blockIdx.x;
    int g = o >> 6, ol = o & 63;
    if (threadIdx.x < 64) wz[threadIdx.x] = Wz[g * 4096 + ol * 64 + threadIdx.x];
    __syncthreads();
    for (int c = threadIdx.x; c < NC; c += 128) {
        float a = 0.f;
#pragma unroll 16
        for (int cl = 0; cl < 64; ++cl)
            a = fmaf(wz[cl], Wt[(g * 64 + cl) * NC + c], a);
        g_wzt[o * NC + c] = a;
    }
}

// M_g[c, c'] = sum_oc Wp[g*64+oc, c] * Wg[g*64+oc, c']   (fp32 exact)
__global__ void m_kernel(const float* __restrict__ Wp, const float* __restrict__ Wg) {
    __shared__ float wp[64][33];
    __shared__ float wg[64][33];
    int ct = blockIdx.x, cpt = blockIdx.y, g = blockIdx.z;
    int tid = threadIdx.x;
#pragma unroll
    for (int j = 0; j < 8; ++j) {
        int idx = tid + 256 * j;
        int oc = idx >> 5, cl = idx & 31;
        wp[oc][cl] = Wp[(g * 64 + oc) * NC + ct * 32 + cl];
        wg[oc][cl] = Wg[(g * 64 + oc) * NC + cpt * 32 + cl];
    }
    __syncthreads();
    int cl = tid >> 3, cp4 = (tid & 7) << 2;
    float acc[4] = {0.f, 0.f, 0.f, 0.f};
#pragma unroll 16
    for (int oc = 0; oc < 64; ++oc) {
        float a = wp[oc][cl];
        acc[0] = fmaf(a, wg[oc][cp4 + 0], acc[0]);
        acc[1] = fmaf(a, wg[oc][cp4 + 1], acc[1]);
        acc[2] = fmaf(a, wg[oc][cp4 + 2], acc[2]);
        acc[3] = fmaf(a, wg[oc][cp4 + 3], acc[3]);
    }
    float4 o = make_float4(acc[0], acc[1], acc[2], acc[3]);
    *reinterpret_cast<float4*>(&g_m[((size_t)g << 18) + (size_t)(ct * 32 + cl) * NC + cpt * 32 + cp4]) = o;
}

// =========================================================================
// S kernel: S_b = Q_b @ K_b^T  (512x512x1024 per batch), 3xTF32 precision.
// Tile 128x128, BK=16, double-buffered cp.async, SINGLE barrier per k-iter:
//   wait(0); sync; issue(kc+1) async; compute(kc)
// 8 warps as 2(m) x 4(n), warp tile 64x32.
// =========================================================================
#define S_ST 20
#define S_STAGE (256 * S_ST)   // 5120 floats (A tile + B tile)

__device__ __forceinline__ void s_issue(float* st, const float* Ab, const float* Bb,
                                        int kc, int tid) {
    float* As = st;
    float* Bs = st + 128 * S_ST;
#pragma unroll
    for (int i = 0; i < 2; ++i) {
        int c = tid + 256 * i;
        int r = c >> 2, kq = (c & 3) << 2;     // 128 rows x 16 k
        CP_ASYNC16(smem_u32(As + r * S_ST + kq), Ab + r * ND + kc * 16 + kq);
    }
#pragma unroll
    for (int i = 0; i < 2; ++i) {
        int c = tid + 256 * i;
        int r = c >> 2, kq = (c & 3) << 2;
        CP_ASYNC16(smem_u32(Bs + r * S_ST + kq), Bb + r * ND + kc * 16 + kq);
    }
}

__device__ __forceinline__ void s_compute(const float* st, float acc[4][4][4],
                                          int wm, int wn, int gid, int t4) {
    const float* As = st;
    const float* Bs = st + 128 * S_ST;
#pragma unroll
    for (int ks = 0; ks < 2; ++ks) {
        const int k = ks * 8;
        uint32_t bb[4][2], bs[4][2];
#pragma unroll
        for (int ni = 0; ni < 4; ++ni) {
            int n = wn * 32 + ni * 8 + gid;
            float b0 = Bs[n * S_ST + k + t4];
            float b1 = Bs[n * S_ST + k + t4 + 4];
            bb[ni][0] = tf32_big(b0); bs[ni][0] = tf32_small(b0, bb[ni][0]);
            bb[ni][1] = tf32_big(b1); bs[ni][1] = tf32_small(b1, bb[ni][1]);
        }
#pragma unroll
        for (int mi = 0; mi < 4; ++mi) {
            int r = wm * 64 + mi * 16 + gid;
            float a0 = As[r * S_ST + k + t4];
            float a1 = As[(r + 8) * S_ST + k + t4];
            float a2 = As[r * S_ST + k + t4 + 4];
            float a3 = As[(r + 8) * S_ST + k + t4 + 4];
            uint32_t ab[4], as_[4];
            ab[0] = tf32_big(a0); as_[0] = tf32_small(a0, ab[0]);
            ab[1] = tf32_big(a1); as_[1] = tf32_small(a1, ab[1]);
            ab[2] = tf32_big(a2); as_[2] = tf32_small(a2, ab[2]);
            ab[3] = tf32_big(a3); as_[3] = tf32_small(a3, ab[3]);
#pragma unroll
            for (int ni = 0; ni < 4; ++ni) {
                mma_tf32(acc[mi][ni], as_, bb[ni]);   // small_a * big_b
                mma_tf32(acc[mi][ni], ab,  bs[ni]);   // big_a * small_b
                mma_tf32(acc[mi][ni], ab,  bb[ni]);   // big_a * big_b
            }
        }
    }
}

__global__ __launch_bounds__(256, 2) void s_gemm_kernel(const float* __restrict__ Q,
                                                        const float* __restrict__ Kk) {
    __shared__ float sm[2 * S_STAGE];
    const int tid = threadIdx.x;
    const int mt = blockIdx.x, nt = blockIdx.y, b = blockIdx.z;
    const int lane = tid & 31, w = tid >> 5;
    const int wm = w & 1, wn = w >> 1;          // 2 x 4 warp grid
    const int gid = lane >> 2, t4 = lane & 3;

    const float* Ab = Q  + (size_t)b * NC * ND + (size_t)(mt * 128) * ND;
    const float* Bb = Kk + (size_t)b * NC * ND + (size_t)(nt * 128) * ND;

    float acc[4][4][4] = {};
    s_issue(sm, Ab, Bb, 0, tid);
    CP_COMMIT();
#pragma unroll 1
    for (int kc = 0; kc < 64; ++kc) {
        CP_WAIT(0);
        __syncthreads();
        if (kc < 63) {
            s_issue(sm + ((kc + 1) & 1) * S_STAGE, Ab, Bb, kc + 1, tid);
            CP_COMMIT();
        }
        s_compute(sm + (kc & 1) * S_STAGE, acc, wm, wn, gid, t4);
    }

    float* Sb = g_s + ((size_t)b << 18) + (size_t)(mt * 128) * NC + nt * 128;
#pragma unroll
    for (int mi = 0; mi < 4; ++mi) {
#pragma unroll
        for (int ni = 0; ni < 4; ++ni) {
            int r  = wm * 64 + mi * 16 + gid;
            int cc = wn * 32 + ni * 8 + t4 * 2;
            *reinterpret_cast<float2*>(Sb + (size_t)r * NC + cc)       = make_float2(acc[mi][ni][0], acc[mi][ni][1]);
            *reinterpret_cast<float2*>(Sb + (size_t)(r + 8) * NC + cc) = make_float2(acc[mi][ni][2], acc[mi][ni][3]);
        }
    }
}

// att[b,g] = sum_i M_g[i] * S_b[i]  over 512*512 elements.
// grid 256 blocks (k-chunks of 1024 floats), 8 warps; warp w owns group g=w,
// its M chunk hoisted into 8 float4 registers; S streamed once (L1-shared
// across the 8 warps).
__global__ void att_reduce_kernel() {
    int tid = threadIdx.x;
    int w = tid >> 5, l = tid & 31;            // w = group
    size_t base4 = (size_t)blockIdx.x * 256;   // float4 units
    const float4* M4 = reinterpret_cast<const float4*>(g_m) + (size_t)w * 65536 + base4;
    const float4* S4b = reinterpret_cast<const float4*>(g_s);
    float4 m[8];
#pragma unroll
    for (int j = 0; j < 8; ++j) m[j] = M4[l + 32 * j];
#pragma unroll 1
    for (int b = 0; b < NB; ++b) {
        const float4* S4 = S4b + (size_t)b * 65536 + base4;
        float acc = 0.f;
#pragma unroll
        for (int j = 0; j < 8; ++j) {
            float4 s = S4[l + 32 * j];
            acc = fmaf(m[j].x, s.x, acc);
            acc = fmaf(m[j].y, s.y, acc);
            acc = fmaf(m[j].z, s.z, acc);
            acc = fmaf(m[j].w, s.w, acc);
        }
#pragma unroll
        for (int off = 16; off > 0; off >>= 1)
            acc += __shfl_xor_sync(0xffffffffu, acc, off);
        if (l == 0) atomicAdd(&g_att[b * NG + w], acc);
    }
}

// =========================================================================
// u kernel: u = Wzt @ v per batch, tile 128x128, BK=16, plain tf32; fused
// GroupNorm stats in the epilogue. Single barrier per k-iter (same pipeline
// as s_gemm). 8 warps as 2(m) x 4(n), warp tile 64x32.
// =========================================================================
#define U_AS 20
#define U_BS 136
#define U_STAGE (128 * U_AS + 16 * U_BS)   // 4736 floats

__device__ __forceinline__ void u_issue(float* st, const float* Ab, const float* Bb,
                                        int kc, int tid) {
    float* As = st;
    float* Bs = st + 128 * U_AS;
#pragma unroll
    for (int i = 0; i < 2; ++i) {
        int c = tid + 256 * i;
        int r = c >> 2, kq = (c & 3) << 2;
        CP_ASYNC16(smem_u32(As + r * U_AS + kq), Ab + r * 512 + kc * 16 + kq);
    }
#pragma unroll
    for (int i = 0; i < 2; ++i) {
        int c = tid + 256 * i;
        int kr = c >> 5, dq = (c & 31) << 2;   // 16 rows x 128 d
        CP_ASYNC16(smem_u32(Bs + kr * U_BS + dq), Bb + (kc * 16 + kr) * 1024 + dq);
    }
}

__device__ __forceinline__ void u_compute(const float* st, float acc[4][4][4],
                                          int wm, int wn, int gid, int t4) {
    const float* As = st;
    const float* Bs = st + 128 * U_AS;
#pragma unroll
    for (int ks = 0; ks < 2; ++ks) {
        const int k = ks * 8;
        uint32_t af[4][4], bf[4][2];
#pragma unroll
        for (int mi = 0; mi < 4; ++mi) {
            int r = wm * 64 + mi * 16 + gid;
            af[mi][0] = __float_as_uint(As[r * U_AS + k + t4]);
            af[mi][1] = __float_as_uint(As[(r + 8) * U_AS + k + t4]);
            af[mi][2] = __float_as_uint(As[r * U_AS + k + t4 + 4]);
            af[mi][3] = __float_as_uint(As[(r + 8) * U_AS + k + t4 + 4]);
        }
#pragma unroll
        for (int ni = 0; ni < 4; ++ni) {
            int cc = wn * 32 + ni * 8 + gid;
            bf[ni][0] = __float_as_uint(Bs[(k + t4) * U_BS + cc]);
            bf[ni][1] = __float_as_uint(Bs[(k + t4 + 4) * U_BS + cc]);
        }
#pragma unroll
        for (int mi = 0; mi < 4; ++mi)
#pragma unroll
            for (int ni = 0; ni < 4; ++ni)
                mma_tf32(acc[mi][ni], af[mi], bf[ni]);
    }
}

__global__ __launch_bounds__(256, 2) void u_gemm_kernel(const float* __restrict__ V) {
    __shared__ float sm[2 * U_STAGE];
    const int tid = threadIdx.x;
    const int mt = blockIdx.x, dt = blockIdx.y, b = blockIdx.z;
    const int lane = tid & 31, w = tid >> 5;
    const int wm = w & 1, wn = w >> 1;          // 2 x 4 warp grid
    const int gid = lane >> 2, t4 = lane & 3;

    const float* Ab = g_wzt + mt * 128 * 512;
    const float* Bb = V + (size_t)b * NC * ND + dt * 128;

    float acc[4][4][4] = {};
    u_issue(sm, Ab, Bb, 0, tid);
    CP_COMMIT();
#pragma unroll 1
    for (int kc = 0; kc < 32; ++kc) {
        CP_WAIT(0);
        __syncthreads();
        if (kc < 31) {
            u_issue(sm + ((kc + 1) & 1) * U_STAGE, Ab, Bb, kc + 1, tid);
            CP_COMMIT();
        }
        u_compute(sm + (kc & 1) * U_STAGE, acc, wm, wn, gid, t4);
    }

    // epilogue: store u + accumulate per-(b,g) sum / sumsq
    float s = 0.f, s2 = 0.f;
    float* Ub = g_u + ((size_t)b * NC + mt * 128) * ND + dt * 128;
#pragma unroll
    for (int mi = 0; mi < 4; ++mi) {
#pragma unroll
        for (int ni = 0; ni < 4; ++ni) {
            int r  = wm * 64 + mi * 16 + gid;
            int cc = wn * 32 + ni * 8 + t4 * 2;
            float c0 = acc[mi][ni][0], c1 = acc[mi][ni][1];
            float c2 = acc[mi][ni][2], c3 = acc[mi][ni][3];
            *reinterpret_cast<float2*>(Ub + (size_t)r * ND + cc)       = make_float2(c0, c1);
            *reinterpret_cast<float2*>(Ub + (size_t)(r + 8) * ND + cc) = make_float2(c2, c3);
            s  += (c0 + c1) + (c2 + c3);
            s2 += c0 * c0 + c1 * c1 + c2 * c2 + c3 * c3;
        }
    }
#pragma unroll
    for (int off = 16; off > 0; off >>= 1) {
        s  += __shfl_xor_sync(0xffffffffu, s, off);
        s2 += __shfl_xor_sync(0xffffffffu, s2, off);
    }
    if (lane == 0) {
        int gi = b * NG + mt * 2 + wm;
        atomicAdd(&g_sums[gi], s);
        atomicAdd(&g_sumsq[gi], s2);
    }
}

// ---------------- coefficient + final streaming pass ----------------
// xn = (att*u - att*mean_u) * rsqrt(att^2*var_u + eps)
// out = gamma*xn + beta + v  ==  cA*u + cB + v
__global__ void coef_kernel(const float* __restrict__ gamma, const float* __restrict__ beta) {
    int b = blockIdx.x, c = threadIdx.x;
    int g = c >> 6;
    float mean = g_sums[b * NG + g] * (1.0f / 65536.0f);
    float var  = g_sumsq[b * NG + g] * (1.0f / 65536.0f) - mean * mean;
    var = fmaxf(var, 0.f);
    float a = g_att[b * NG + g] * 0.125f;
    float inv = rsqrtf(a * a * var + 1e-5f);
    float cA = gamma[c] * a * inv;
    g_cA[b * NC + c] = cA;
    g_cB[b * NC + c] = beta[c] - cA * mean;
}

__global__ void final_kernel(const float4* __restrict__ V4, float4* __restrict__ O4) {
    int i = blockIdx.x * 256 + threadIdx.x;   // one float4 along d
    int row = i >> 8;                          // b*512 + c
    float cA = g_cA[row];
    float cB = g_cB[row];
    const float4* U4 = reinterpret_cast<const float4*>(g_u);
    float4 u = U4[i];
    float4 v = V4[i];
    float4 o;
    o.x = fmaf(cA, u.x, cB) + v.x;
    o.y = fmaf(cA, u.y, cB) + v.y;
    o.z = fmaf(cA, u.z, cB) + v.z;
    o.w = fmaf(cA, u.w, cB) + v.w;
    O4[i] = o;
}

// ---------------- launch ----------------
extern "C" void kernel_launch(void* const* d_in, const int* in_sizes, int n_in,
                              void* d_out, int out_size) {
    (void)in_sizes; (void)n_in; (void)out_size;
    const float* q     = (const float*)d_in[0];
    const float* k     = (const float*)d_in[1];
    const float* v     = (const float*)d_in[2];
    const float* Wt    = (const float*)d_in[3];
    const float* Wp    = (const float*)d_in[4];
    const float* Wg    = (const float*)d_in[5];
    const float* Wz    = (const float*)d_in[6];
    const float* gamma = (const float*)d_in[7];
    const float* beta  = (const float*)d_in[8];
    float* out = (float*)d_out;

    zero_kernel<<<1, 512>>>();
    wzt_kernel<<<512, 128>>>(Wt, Wz);
    m_kernel<<<dim3(16, 16, 8), 256>>>(Wp, Wg);
    s_gemm_kernel<<<dim3(4, 4, 64), 256>>>(q, k);
    att_reduce_kernel<<<256, 256>>>();
    u_gemm_kernel<<<dim3(4, 8, 64), 256>>>(v);
    coef_kernel<<<64, 512>>>(gamma, beta);
    final_kernel<<<32768, 256>>>(reinterpret_cast<const float4*>(v),
                                 reinterpret_cast<float4*>(out));
}

// round 11
// speedup vs baseline: 1.1726x; 1.1726x over previous
#include <cuda_runtime.h>
#include <cstdint>
#include <cstddef>

#define NB 64
#define NC 512
#define ND 1024
#define NG 8

// ---------------- scratch (device globals: no allocation allowed) ----------------
__device__ float g_u[(size_t)NB * NC * ND];     // 128 MB: u = Wzt @ v
__device__ float g_s[(size_t)NB * NC * NC];     // 64 MB: S_b = Q_b K_b^T
__device__ float g_m[(size_t)NG * NC * NC];     // 8 MB:  M_g = Wp_g^T Wg_g
__device__ float g_wzt[NC * NC];                // blockdiag(Wz) @ Wt
__device__ float g_att[NB * NG];
__device__ float g_sums[NB * NG];
__device__ float g_sumsq[NB * NG];
__device__ float g_cA[NB * NC];
__device__ float g_cB[NB * NC];

// ---------------- helpers ----------------
__device__ __forceinline__ uint32_t smem_u32(const void* p) {
    return (uint32_t)__cvta_generic_to_shared(p);
}
#define CP_ASYNC16(dst, src) \
    asm volatile("cp.async.ca.shared.global [%0], [%1], 16;" :: "r"(dst), "l"(src) : "memory")
#define CP_COMMIT() asm volatile("cp.async.commit_group;" ::: "memory")
#define CP_WAIT(n)  asm volatile("cp.async.wait_group %0;" :: "n"(n) : "memory")

__device__ __forceinline__ void mma_tf32(float c[4], const uint32_t a[4], const uint32_t b[2]) {
    asm volatile(
        "mma.sync.aligned.m16n8k8.row.col.f32.tf32.tf32.f32 "
        "{%0,%1,%2,%3}, {%4,%5,%6,%7}, {%8,%9}, {%0,%1,%2,%3};"
        : "+f"(c[0]), "+f"(c[1]), "+f"(c[2]), "+f"(c[3])
        : "r"(a[0]), "r"(a[1]), "r"(a[2]), "r"(a[3]), "r"(b[0]), "r"(b[1]));
}

__device__ __forceinline__ void mma_bf16(float c[4], const uint32_t a[4], const uint32_t b[2]) {
    asm volatile(
        "mma.sync.aligned.m16n8k16.row.col.f32.bf16.bf16.f32 "
        "{%0,%1,%2,%3}, {%4,%5,%6,%7}, {%8,%9}, {%0,%1,%2,%3};"
        : "+f"(c[0]), "+f"(c[1]), "+f"(c[2]), "+f"(c[3])
        : "r"(a[0]), "r"(a[1]), "r"(a[2]), "r"(a[3]), "r"(b[0]), "r"(b[1]));
}

// Split fp32 pair (x = even k, y = odd k) into packed bf16x2 hi (truncated
// top-16-bits) and bf16x2 lo (residual). hi/lo low half = x, high half = y.
__device__ __forceinline__ void bsplit2(float x, float y, uint32_t& hi, uint32_t& lo) {
    uint32_t xb = __float_as_uint(x), yb = __float_as_uint(y);
    float xr = x - __uint_as_float(xb & 0xFFFF0000u);
    float yr = y - __uint_as_float(yb & 0xFFFF0000u);
    asm("prmt.b32 %0,%1,%2,0x7632;" : "=r"(hi) : "r"(xb), "r"(yb));
    asm("prmt.b32 %0,%1,%2,0x7632;" : "=r"(lo)
        : "r"(__float_as_uint(xr)), "r"(__float_as_uint(yr)));
}

// ---------------- tiny kernels ----------------
__global__ void zero_kernel() {
    int i = threadIdx.x;  // 512 = NB*NG
    g_att[i] = 0.f; g_sums[i] = 0.f; g_sumsq[i] = 0.f;
}

// Wzt[o, c] = sum_cl Wz[g, o%64, cl] * Wt[g*64 + cl, c],  g = o/64
__global__ void wzt_kernel(const float* __restrict__ Wt, const float* __restrict__ Wz) {
    __shared__ float wz[64];
    int o = blockIdx.x;
    int g = o >> 6, ol = o & 63;
    if (threadIdx.x < 64) wz[threadIdx.x] = Wz[g * 4096 + ol * 64 + threadIdx.x];
    __syncthreads();
    for (int c = threadIdx.x; c < NC; c += 128) {
        float a = 0.f;
#pragma unroll 16
        for (int cl = 0; cl < 64; ++cl)
            a = fmaf(wz[cl], Wt[(g * 64 + cl) * NC + c], a);
        g_wzt[o * NC + c] = a;
    }
}

// M_g[c, c'] = sum_oc Wp[g*64+oc, c] * Wg[g*64+oc, c']   (fp32 exact)
__global__ void m_kernel(const float* __restrict__ Wp, const float* __restrict__ Wg) {
    __shared__ float wp[64][33];
    __shared__ float wg[64][33];
    int ct = blockIdx.x, cpt = blockIdx.y, g = blockIdx.z;
    int tid = threadIdx.x;
#pragma unroll
    for (int j = 0; j < 8; ++j) {
        int idx = tid + 256 * j;
        int oc = idx >> 5, cl = idx & 31;
        wp[oc][cl] = Wp[(g * 64 + oc) * NC + ct * 32 + cl];
        wg[oc][cl] = Wg[(g * 64 + oc) * NC + cpt * 32 + cl];
    }
    __syncthreads();
    int cl = tid >> 3, cp4 = (tid & 7) << 2;
    float acc[4] = {0.f, 0.f, 0.f, 0.f};
#pragma unroll 16
    for (int oc = 0; oc < 64; ++oc) {
        float a = wp[oc][cl];
        acc[0] = fmaf(a, wg[oc][cp4 + 0], acc[0]);
        acc[1] = fmaf(a, wg[oc][cp4 + 1], acc[1]);
        acc[2] = fmaf(a, wg[oc][cp4 + 2], acc[2]);
        acc[3] = fmaf(a, wg[oc][cp4 + 3], acc[3]);
    }
    float4 o = make_float4(acc[0], acc[1], acc[2], acc[3]);
    *reinterpret_cast<float4*>(&g_m[((size_t)g << 18) + (size_t)(ct * 32 + cl) * NC + cpt * 32 + cp4]) = o;
}

// =========================================================================
// S kernel: S_b = Q_b @ K_b^T  (512x512x1024 per batch), bf16x2 precision
// (Ootomo split: ah*bh + ah*bl + al*bh via m16n8k16 -> ~2^-16 relative).
// Tile 128x128, BK=16, double-buffered cp.async, single barrier per k-iter.
// 8 warps as 2(m) x 4(n), warp tile 64x32.
// Smem [row][k] stride 24 floats: float2 access (r*12 + t4 in 8B units) is
// bank-conflict-free mod 16; 2 stages * 256 rows * 24 * 4B = 49152 B exact.
// =========================================================================
#define S_ST 24
#define S_STAGE (256 * S_ST)   // 6144 floats (A tile + B tile)

__device__ __forceinline__ void s_issue(float* st, const float* Ab, const float* Bb,
                                        int kc, int tid) {
    float* As = st;
    float* Bs = st + 128 * S_ST;
#pragma unroll
    for (int i = 0; i < 2; ++i) {
        int c = tid + 256 * i;
        int r = c >> 2, kq = (c & 3) << 2;     // 128 rows x 16 k
        CP_ASYNC16(smem_u32(As + r * S_ST + kq), Ab + r * ND + kc * 16 + kq);
    }
#pragma unroll
    for (int i = 0; i < 2; ++i) {
        int c = tid + 256 * i;
        int r = c >> 2, kq = (c & 3) << 2;
        CP_ASYNC16(smem_u32(Bs + r * S_ST + kq), Bb + r * ND + kc * 16 + kq);
    }
}

// one k16 chunk per call
__device__ __forceinline__ void s_compute(const float* st, float acc[4][4][4],
                                          int wm, int wn, int gid, int t4) {
    const float* As = st;
    const float* Bs = st + 128 * S_ST;
    uint32_t bhi[4][2], blo[4][2];
#pragma unroll
    for (int ni = 0; ni < 4; ++ni) {
        int n = wn * 32 + ni * 8 + gid;
        float2 b0 = *reinterpret_cast<const float2*>(Bs + n * S_ST + 2 * t4);
        float2 b1 = *reinterpret_cast<const float2*>(Bs + n * S_ST + 8 + 2 * t4);
        bsplit2(b0.x, b0.y, bhi[ni][0], blo[ni][0]);
        bsplit2(b1.x, b1.y, bhi[ni][1], blo[ni][1]);
    }
#pragma unroll
    for (int mi = 0; mi < 4; ++mi) {
        int r = wm * 64 + mi * 16 + gid;
        float2 a00 = *reinterpret_cast<const float2*>(As + r * S_ST + 2 * t4);
        float2 a10 = *reinterpret_cast<const float2*>(As + (r + 8) * S_ST + 2 * t4);
        float2 a01 = *reinterpret_cast<const float2*>(As + r * S_ST + 8 + 2 * t4);
        float2 a11 = *reinterpret_cast<const float2*>(As + (r + 8) * S_ST + 8 + 2 * t4);
        uint32_t ahi[4], alo[4];
        bsplit2(a00.x, a00.y, ahi[0], alo[0]);   // a0: row r,   k 2t4..
        bsplit2(a10.x, a10.y, ahi[1], alo[1]);   // a1: row r+8, k 2t4..
        bsplit2(a01.x, a01.y, ahi[2], alo[2]);   // a2: row r,   k 8+2t4..
        bsplit2(a11.x, a11.y, ahi[3], alo[3]);   // a3: row r+8, k 8+2t4..
#pragma unroll
        for (int ni = 0; ni < 4; ++ni) {
            mma_bf16(acc[mi][ni], alo, bhi[ni]);   // lo_a * hi_b
            mma_bf16(acc[mi][ni], ahi, blo[ni]);   // hi_a * lo_b
            mma_bf16(acc[mi][ni], ahi, bhi[ni]);   // hi_a * hi_b
        }
    }
}

__global__ __launch_bounds__(256, 2) void s_gemm_kernel(const float* __restrict__ Q,
                                                        const float* __restrict__ Kk) {
    __shared__ float sm[2 * S_STAGE];
    const int tid = threadIdx.x;
    const int mt = blockIdx.x, nt = blockIdx.y, b = blockIdx.z;
    const int lane = tid & 31, w = tid >> 5;
    const int wm = w & 1, wn = w >> 1;          // 2 x 4 warp grid
    const int gid = lane >> 2, t4 = lane & 3;

    const float* Ab = Q  + (size_t)b * NC * ND + (size_t)(mt * 128) * ND;
    const float* Bb = Kk + (size_t)b * NC * ND + (size_t)(nt * 128) * ND;

    float acc[4][4][4] = {};
    s_issue(sm, Ab, Bb, 0, tid);
    CP_COMMIT();
#pragma unroll 1
    for (int kc = 0; kc < 64; ++kc) {
        CP_WAIT(0);
        __syncthreads();
        if (kc < 63) {
            s_issue(sm + ((kc + 1) & 1) * S_STAGE, Ab, Bb, kc + 1, tid);
            CP_COMMIT();
        }
        s_compute(sm + (kc & 1) * S_STAGE, acc, wm, wn, gid, t4);
    }

    float* Sb = g_s + ((size_t)b << 18) + (size_t)(mt * 128) * NC + nt * 128;
#pragma unroll
    for (int mi = 0; mi < 4; ++mi) {
#pragma unroll
        for (int ni = 0; ni < 4; ++ni) {
            int r  = wm * 64 + mi * 16 + gid;
            int cc = wn * 32 + ni * 8 + t4 * 2;
            *reinterpret_cast<float2*>(Sb + (size_t)r * NC + cc)       = make_float2(acc[mi][ni][0], acc[mi][ni][1]);
            *reinterpret_cast<float2*>(Sb + (size_t)(r + 8) * NC + cc) = make_float2(acc[mi][ni][2], acc[mi][ni][3]);
        }
    }
}

// att[b,g] = sum_i M_g[i] * S_b[i]  over 512*512 elements.
// grid 256 blocks (k-chunks of 1024 floats), 8 warps; warp w owns group g=w,
// its M chunk hoisted into 8 float4 registers; S streamed once (L1-shared
// across the 8 warps).
__global__ void att_reduce_kernel() {
    int tid = threadIdx.x;
    int w = tid >> 5, l = tid & 31;            // w = group
    size_t base4 = (size_t)blockIdx.x * 256;   // float4 units
    const float4* M4 = reinterpret_cast<const float4*>(g_m) + (size_t)w * 65536 + base4;
    const float4* S4b = reinterpret_cast<const float4*>(g_s);
    float4 m[8];
#pragma unroll
    for (int j = 0; j < 8; ++j) m[j] = M4[l + 32 * j];
#pragma unroll 1
    for (int b = 0; b < NB; ++b) {
        const float4* S4 = S4b + (size_t)b * 65536 + base4;
        float acc = 0.f;
#pragma unroll
        for (int j = 0; j < 8; ++j) {
            float4 s = S4[l + 32 * j];
            acc = fmaf(m[j].x, s.x, acc);
            acc = fmaf(m[j].y, s.y, acc);
            acc = fmaf(m[j].z, s.z, acc);
            acc = fmaf(m[j].w, s.w, acc);
        }
#pragma unroll
        for (int off = 16; off > 0; off >>= 1)
            acc += __shfl_xor_sync(0xffffffffu, acc, off);
        if (l == 0) atomicAdd(&g_att[b * NG + w], acc);
    }
}

// =========================================================================
// u kernel: u = Wzt @ v per batch, tile 128x128, BK=16, plain tf32
// (measured contribution ~1.05e-4, under gate); fused GroupNorm stats in
// the epilogue. 8 warps as 2(m) x 4(n), warp tile 64x32.
// =========================================================================
#define U_AS 20
#define U_BS 136
#define U_STAGE (128 * U_AS + 16 * U_BS)   // 4736 floats

__device__ __forceinline__ void u_issue(float* st, const float* Ab, const float* Bb,
                                        int kc, int tid) {
    float* As = st;
    float* Bs = st + 128 * U_AS;
#pragma unroll
    for (int i = 0; i < 2; ++i) {
        int c = tid + 256 * i;
        int r = c >> 2, kq = (c & 3) << 2;
        CP_ASYNC16(smem_u32(As + r * U_AS + kq), Ab + r * 512 + kc * 16 + kq);
    }
#pragma unroll
    for (int i = 0; i < 2; ++i) {
        int c = tid + 256 * i;
        int kr = c >> 5, dq = (c & 31) << 2;   // 16 rows x 128 d
        CP_ASYNC16(smem_u32(Bs + kr * U_BS + dq), Bb + (kc * 16 + kr) * 1024 + dq);
    }
}

__device__ __forceinline__ void u_compute(const float* st, float acc[4][4][4],
                                          int wm, int wn, int gid, int t4) {
    const float* As = st;
    const float* Bs = st + 128 * U_AS;
#pragma unroll
    for (int ks = 0; ks < 2; ++ks) {
        const int k = ks * 8;
        uint32_t af[4][4], bf[4][2];
#pragma unroll
        for (int mi = 0; mi < 4; ++mi) {
            int r = wm * 64 + mi * 16 + gid;
            af[mi][0] = __float_as_uint(As[r * U_AS + k + t4]);
            af[mi][1] = __float_as_uint(As[(r + 8) * U_AS + k + t4]);
            af[mi][2] = __float_as_uint(As[r * U_AS + k + t4 + 4]);
            af[mi][3] = __float_as_uint(As[(r + 8) * U_AS + k + t4 + 4]);
        }
#pragma unroll
        for (int ni = 0; ni < 4; ++ni) {
            int cc = wn * 32 + ni * 8 + gid;
            bf[ni][0] = __float_as_uint(Bs[(k + t4) * U_BS + cc]);
            bf[ni][1] = __float_as_uint(Bs[(k + t4 + 4) * U_BS + cc]);
        }
#pragma unroll
        for (int mi = 0; mi < 4; ++mi)
#pragma unroll
            for (int ni = 0; ni < 4; ++ni)
                mma_tf32(acc[mi][ni], af[mi], bf[ni]);
    }
}

__global__ __launch_bounds__(256, 2) void u_gemm_kernel(const float* __restrict__ V) {
    __shared__ float sm[2 * U_STAGE];
    const int tid = threadIdx.x;
    const int mt = blockIdx.x, dt = blockIdx.y, b = blockIdx.z;
    const int lane = tid & 31, w = tid >> 5;
    const int wm = w & 1, wn = w >> 1;          // 2 x 4 warp grid
    const int gid = lane >> 2, t4 = lane & 3;

    const float* Ab = g_wzt + mt * 128 * 512;
    const float* Bb = V + (size_t)b * NC * ND + dt * 128;

    float acc[4][4][4] = {};
    u_issue(sm, Ab, Bb, 0, tid);
    CP_COMMIT();
#pragma unroll 1
    for (int kc = 0; kc < 32; ++kc) {
        CP_WAIT(0);
        __syncthreads();
        if (kc < 31) {
            u_issue(sm + ((kc + 1) & 1) * U_STAGE, Ab, Bb, kc + 1, tid);
            CP_COMMIT();
        }
        u_compute(sm + (kc & 1) * U_STAGE, acc, wm, wn, gid, t4);
    }

    // epilogue: store u + accumulate per-(b,g) sum / sumsq
    float s = 0.f, s2 = 0.f;
    float* Ub = g_u + ((size_t)b * NC + mt * 128) * ND + dt * 128;
#pragma unroll
    for (int mi = 0; mi < 4; ++mi) {
#pragma unroll
        for (int ni = 0; ni < 4; ++ni) {
            int r  = wm * 64 + mi * 16 + gid;
            int cc = wn * 32 + ni * 8 + t4 * 2;
            float c0 = acc[mi][ni][0], c1 = acc[mi][ni][1];
            float c2 = acc[mi][ni][2], c3 = acc[mi][ni][3];
            *reinterpret_cast<float2*>(Ub + (size_t)r * ND + cc)       = make_float2(c0, c1);
            *reinterpret_cast<float2*>(Ub + (size_t)(r + 8) * ND + cc) = make_float2(c2, c3);
            s  += (c0 + c1) + (c2 + c3);
            s2 += c0 * c0 + c1 * c1 + c2 * c2 + c3 * c3;
        }
    }
#pragma unroll
    for (int off = 16; off > 0; off >>= 1) {
        s  += __shfl_xor_sync(0xffffffffu, s, off);
        s2 += __shfl_xor_sync(0xffffffffu, s2, off);
    }
    if (lane == 0) {
        int gi = b * NG + mt * 2 + wm;
        atomicAdd(&g_sums[gi], s);
        atomicAdd(&g_sumsq[gi], s2);
    }
}

// ---------------- coefficient + final streaming pass ----------------
// xn = (att*u - att*mean_u) * rsqrt(att^2*var_u + eps)
// out = gamma*xn + beta + v  ==  cA*u + cB + v
__global__ void coef_kernel(const float* __restrict__ gamma, const float* __restrict__ beta) {
    int b = blockIdx.x, c = threadIdx.x;
    int g = c >> 6;
    float mean = g_sums[b * NG + g] * (1.0f / 65536.0f);
    float var  = g_sumsq[b * NG + g] * (1.0f / 65536.0f) - mean * mean;
    var = fmaxf(var, 0.f);
    float a = g_att[b * NG + g] * 0.125f;
    float inv = rsqrtf(a * a * var + 1e-5f);
    float cA = gamma[c] * a * inv;
    g_cA[b * NC + c] = cA;
    g_cB[b * NC + c] = beta[c] - cA * mean;
}

__global__ void final_kernel(const float4* __restrict__ V4, float4* __restrict__ O4) {
    int i = blockIdx.x * 256 + threadIdx.x;   // one float4 along d
    int row = i >> 8;                          // b*512 + c
    float cA = g_cA[row];
    float cB = g_cB[row];
    const float4* U4 = reinterpret_cast<const float4*>(g_u);
    float4 u = U4[i];
    float4 v = V4[i];
    float4 o;
    o.x = fmaf(cA, u.x, cB) + v.x;
    o.y = fmaf(cA, u.y, cB) + v.y;
    o.z = fmaf(cA, u.z, cB) + v.z;
    o.w = fmaf(cA, u.w, cB) + v.w;
    O4[i] = o;
}

// ---------------- launch ----------------
extern "C" void kernel_launch(void* const* d_in, const int* in_sizes, int n_in,
                              void* d_out, int out_size) {
    (void)in_sizes; (void)n_in; (void)out_size;
    const float* q     = (const float*)d_in[0];
    const float* k     = (const float*)d_in[1];
    const float* v     = (const float*)d_in[2];
    const float* Wt    = (const float*)d_in[3];
    const float* Wp    = (const float*)d_in[4];
    const float* Wg    = (const float*)d_in[5];
    const float* Wz    = (const float*)d_in[6];
    const float* gamma = (const float*)d_in[7];
    const float* beta  = (const float*)d_in[8];
    float* out = (float*)d_out;

    zero_kernel<<<1, 512>>>();
    wzt_kernel<<<512, 128>>>(Wt, Wz);
    m_kernel<<<dim3(16, 16, 8), 256>>>(Wp, Wg);
    s_gemm_kernel<<<dim3(4, 4, 64), 256>>>(q, k);
    att_reduce_kernel<<<256, 256>>>();
    u_gemm_kernel<<<dim3(4, 8, 64), 256>>>(v);
    coef_kernel<<<64, 512>>>(gamma, beta);
    final_kernel<<<32768, 256>>>(reinterpret_cast<const float4*>(v),
                                 reinterpret_cast<float4*>(out));
}